// round 5
// baseline (speedup 1.0000x reference)
#include <cuda_runtime.h>
#include <cuda_fp16.h>
#include <cstdint>

#define NMAX 100000
#define EMAX 3200000
#define SCAN_BLK 1024

// ---------------- device scratch ----------------
// per node: 128 halves = 256B. half index: lin[c] -> 4*(c>>1)+(c&1); asrc[c] -> 4*(c>>1)+2+(c&1)
__device__ __align__(16) __half g_projh[(size_t)NMAX * 128];
__device__ __align__(16) float  g_y[(size_t)NMAX * 64];
__device__ __align__(16) float4 g_pos4[NMAX];
__device__ int g_count[NMAX];
__device__ int g_incl[NMAX];
__device__ int g_offset[NMAX + 1];
__device__ int g_cursor[NMAX];
__device__ int g_bsum[128];
__device__ int g_bpre[128];
__device__ int g_esrc[EMAX];
__device__ int g_idx64;

// ---------------- detect edge_index dtype ----------------
__global__ void detect_kernel(const int* __restrict__ ei) {
    if (threadIdx.x == 0) {
        int is64 = 1;
        for (int i = 1; i < 256; i += 2)
            if (ei[i] != 0) { is64 = 0; break; }
        g_idx64 = is64;
    }
}

// ---------------- zero histogram + pad pos ----------------
__global__ void prep_kernel(const float* __restrict__ pos, int N) {
    int i = blockIdx.x * blockDim.x + threadIdx.x;
    if (i < N) {
        g_count[i] = 0;
        g_pos4[i] = make_float4(pos[3 * i + 0], pos[3 * i + 1], pos[3 * i + 2], 0.f);
    }
}

// ---------------- histogram of dst ----------------
__global__ __launch_bounds__(256) void hist_kernel(const void* __restrict__ ei, int E) {
    int t = blockIdx.x * blockDim.x + threadIdx.x;
    if (t >= E) return;
    int d;
    if (g_idx64) d = (int)((const long long*)ei)[(size_t)E + t];
    else         d = ((const int*)ei)[(size_t)E + t];
    atomicAdd(&g_count[d], 1);
}

// ---------------- scan phase 1 ----------------
__global__ __launch_bounds__(SCAN_BLK) void scan1_kernel(int N) {
    __shared__ int sh[SCAN_BLK];
    int tid = threadIdx.x;
    int i = blockIdx.x * SCAN_BLK + tid;
    int v = (i < N) ? g_count[i] : 0;
    sh[tid] = v;
    __syncthreads();
#pragma unroll
    for (int ofs = 1; ofs < SCAN_BLK; ofs <<= 1) {
        int t = (tid >= ofs) ? sh[tid - ofs] : 0;
        __syncthreads();
        sh[tid] += t;
        __syncthreads();
    }
    if (i < N) g_incl[i] = sh[tid];
    if (tid == SCAN_BLK - 1) g_bsum[blockIdx.x] = sh[tid];
}

// ---------------- scan phase 2 ----------------
__global__ void scan2_kernel(int nb) {
    __shared__ int sh[128];
    int tid = threadIdx.x;
    sh[tid] = (tid < nb) ? g_bsum[tid] : 0;
    __syncthreads();
#pragma unroll
    for (int ofs = 1; ofs < 128; ofs <<= 1) {
        int t = (tid >= ofs) ? sh[tid - ofs] : 0;
        __syncthreads();
        sh[tid] += t;
        __syncthreads();
    }
    if (tid < nb) g_bpre[tid] = sh[tid] - g_bsum[tid];
}

// ---------------- scan phase 3 ----------------
__global__ void scan3_kernel(int N, int E) {
    int i = blockIdx.x * blockDim.x + threadIdx.x;
    if (i < N) {
        int off = g_bpre[i / SCAN_BLK] + g_incl[i] - g_count[i];
        g_offset[i] = off;
        g_cursor[i] = off;
    }
    if (i == 0) g_offset[N] = E;
}

// ---------------- scatter: sort src ids by dst ----------------
__global__ __launch_bounds__(256) void scatter_kernel(const void* __restrict__ ei, int E) {
    int t = blockIdx.x * blockDim.x + threadIdx.x;
    if (t >= E) return;
    int s, d;
    if (g_idx64) {
        s = (int)((const long long*)ei)[t];
        d = (int)((const long long*)ei)[(size_t)E + t];
    } else {
        s = ((const int*)ei)[t];
        d = ((const int*)ei)[(size_t)E + t];
    }
    int idx = atomicAdd(&g_cursor[d], 1);
    g_esrc[idx] = s;
}

// ---------------- node projections (fp16 output, interleaved) ----------------
#define SX_STRIDE 68
__global__ __launch_bounds__(128) void proj_kernel(
    const float* __restrict__ x,
    const float* __restrict__ W_lin,
    const float* __restrict__ W_src,
    int N)
{
    const int c  = threadIdx.x;
    const int m  = c >> 6;
    const int cc = c & 63;
    const int h  = cc >> 4;
    const int k  = cc & 15;
    const int hidx = 4 * (cc >> 1) + (cc & 1) + 2 * m;   // half index within node row
    const float* W = m ? W_src : W_lin;

    float w[64];
#pragma unroll
    for (int j = 0; j < 64; j++) w[j] = __ldg(&W[h * 1024 + j * 16 + k]);

    __shared__ float sx[64 * SX_STRIDE];

    const int base = blockIdx.x * 64;
    for (int f = threadIdx.x; f < 64 * 16; f += 128) {
        int node = f >> 4;
        int j4 = f & 15;
        int gn = base + node;
        if (gn >= N) gn = N - 1;
        float4 v = ((const float4*)x)[(size_t)gn * 16 + j4];
        int j = j4 * 4;
        sx[(j + 0) * SX_STRIDE + node] = v.x;
        sx[(j + 1) * SX_STRIDE + node] = v.y;
        sx[(j + 2) * SX_STRIDE + node] = v.z;
        sx[(j + 3) * SX_STRIDE + node] = v.w;
    }
    __syncthreads();

#pragma unroll
    for (int p = 0; p < 2; p++) {
        float acc[32];
#pragma unroll
        for (int r = 0; r < 32; r++) acc[r] = 0.f;
        for (int j = 0; j < 64; j++) {
            const float4* row = (const float4*)(sx + j * SX_STRIDE + p * 32);
            float wj = w[j];
#pragma unroll
            for (int q = 0; q < 8; q++) {
                float4 v = row[q];
                acc[q * 4 + 0] = fmaf(v.x, wj, acc[q * 4 + 0]);
                acc[q * 4 + 1] = fmaf(v.y, wj, acc[q * 4 + 1]);
                acc[q * 4 + 2] = fmaf(v.z, wj, acc[q * 4 + 2]);
                acc[q * 4 + 3] = fmaf(v.w, wj, acc[q * 4 + 3]);
            }
        }
#pragma unroll
        for (int r = 0; r < 32; r++) {
            int gn = base + p * 32 + r;
            if (gn < N) g_projh[(size_t)gn * 128 + hidx] = __float2half_rn(acc[r]);
        }
    }
}

// ---------------- per-destination-node attention: warp per node ----------------
__global__ __launch_bounds__(256) void node_kernel(
    const float* __restrict__ W_pos,
    const float* __restrict__ b_pos,
    int N)
{
    const int warp = threadIdx.x >> 5;
    const int l = threadIdx.x & 31;
    const int n = blockIdx.x * 8 + warp;
    if (n >= N) return;

    const int c0 = 2 * l;
    const int h  = c0 >> 4;
    const int k0 = c0 & 15;
    const int k1 = k0 + 1;

    const float w00 = __ldg(&W_pos[h * 48 + 0  + k0]);
    const float w10 = __ldg(&W_pos[h * 48 + 16 + k0]);
    const float w20 = __ldg(&W_pos[h * 48 + 32 + k0]);
    const float b0  = __ldg(&b_pos[h * 16 + k0]);
    const float w01 = __ldg(&W_pos[h * 48 + 0  + k1]);
    const float w11 = __ldg(&W_pos[h * 48 + 16 + k1]);
    const float w21 = __ldg(&W_pos[h * 48 + 32 + k1]);
    const float b1  = __ldg(&b_pos[h * 16 + k1]);

    const float4 pn = g_pos4[n];
    const int off = g_offset[n];
    const int end = g_offset[n + 1];

    float den0 = 0.f, den1 = 0.f, ac0 = 0.f, ac1 = 0.f;

    for (int base = off; base < end; base += 32) {
        int idx = base + l;
        int sid = (idx < end) ? g_esrc[idx] : 0;
        int cnt = min(32, end - base);
#pragma unroll 4
        for (int j = 0; j < cnt; j++) {
            int s = __shfl_sync(0xffffffffu, sid, j);
            float4 p = __ldg(&g_pos4[s]);
            uint2 u = __ldg((const uint2*)(g_projh + (size_t)s * 128) + l);
            float2 vl = __half22float2(*(const __half2*)&u.x);  // lin pair
            float2 va = __half22float2(*(const __half2*)&u.y);  // asrc pair

            float rx = p.x - pn.x;
            float ry = p.y - pn.y;
            float rz = p.z - pn.z;

            float d0 = fmaf(rx, w00, fmaf(ry, w10, fmaf(rz, w20, b0)));
            float d1 = fmaf(rx, w01, fmaf(ry, w11, fmaf(rz, w21, b1)));

            float e0 = __expf(va.x + d0);
            float e1 = __expf(va.y + d1);

            den0 += e0;
            den1 += e1;
            ac0 = fmaf(e0, vl.x + d0, ac0);
            ac1 = fmaf(e1, vl.y + d1, ac1);
        }
    }

    float2 r;
    r.x = ac0 / (den0 + 1e-16f);
    r.y = ac1 / (den1 + 1e-16f);
    ((float2*)g_y)[(size_t)n * 32 + l] = r;
}

// ---------------- MLP: out = relu(y@W1+b1)@W2+b2, 64 nodes/block ----------------
__global__ __launch_bounds__(256) void mlp_kernel(
    const float* __restrict__ W1, const float* __restrict__ b1,
    const float* __restrict__ W2, const float* __restrict__ b2,
    float* __restrict__ out, int N)
{
    __shared__ float sW1[4096];
    __shared__ float sW2[4096];
    __shared__ float sy[4][64];
    __shared__ float sh_[4][64];

    for (int i = threadIdx.x; i < 4096; i += 256) {
        sW1[i] = W1[i];
        sW2[i] = W2[i];
    }

    const int i = threadIdx.x >> 6;
    const int o = threadIdx.x & 63;
    const float B1 = __ldg(&b1[o]);
    const float B2 = __ldg(&b2[o]);
    __syncthreads();

    for (int g = 0; g < 16; g++) {
        int n = blockIdx.x * 64 + g * 4 + i;
        float yv = (n < N) ? g_y[(size_t)n * 64 + o] : 0.f;
        sy[i][o] = yv;
        __syncthreads();

        float a = B1;
#pragma unroll
        for (int ci = 0; ci < 64; ci++) a = fmaf(sy[i][ci], sW1[ci * 64 + o], a);
        sh_[i][o] = fmaxf(a, 0.f);
        __syncthreads();

        float r = B2;
#pragma unroll
        for (int ci = 0; ci < 64; ci++) r = fmaf(sh_[i][ci], sW2[ci * 64 + o], r);
        if (n < N) out[(size_t)n * 64 + o] = r;
        __syncthreads();
    }
}

// ---------------- host ----------------
extern "C" void kernel_launch(void* const* d_in, const int* in_sizes, int n_in,
                              void* d_out, int out_size) {
    const float* x     = (const float*)d_in[0];
    const float* pos   = (const float*)d_in[1];
    const void*  ei    = d_in[2];
    const float* W_lin = (const float*)d_in[3];
    const float* W_src = (const float*)d_in[4];
    // d_in[5] = W_dst (cancels in the per-dst softmax)
    const float* W_pos = (const float*)d_in[6];
    const float* b_pos = (const float*)d_in[7];
    const float* W1    = (const float*)d_in[8];
    const float* b1    = (const float*)d_in[9];
    const float* W2    = (const float*)d_in[10];
    const float* b2    = (const float*)d_in[11];
    float* out = (float*)d_out;

    const int N = in_sizes[0] / 64;
    const int E = in_sizes[2] / 2;
    const int nb = (N + SCAN_BLK - 1) / SCAN_BLK;

    detect_kernel<<<1, 32>>>((const int*)ei);
    prep_kernel<<<(N + 255) / 256, 256>>>(pos, N);
    hist_kernel<<<(E + 255) / 256, 256>>>(ei, E);
    scan1_kernel<<<nb, SCAN_BLK>>>(N);
    scan2_kernel<<<1, 128>>>(nb);
    scan3_kernel<<<(N + 255) / 256, 256>>>(N, E);
    scatter_kernel<<<(E + 255) / 256, 256>>>(ei, E);
    proj_kernel<<<(N + 63) / 64, 128>>>(x, W_lin, W_src, N);
    node_kernel<<<(N + 7) / 8, 256>>>(W_pos, b_pos, N);
    mlp_kernel<<<(N + 63) / 64, 256>>>(W1, b1, W2, b2, out, N);
}

// round 6
// speedup vs baseline: 1.0204x; 1.0204x over previous
#include <cuda_runtime.h>
#include <cuda_fp16.h>
#include <cstdint>

#define NMAX 100000
#define EMAX 3200000
#define SCAN_BLK 1024

// ---------------- device scratch ----------------
__device__ __align__(16) __half g_projh[(size_t)NMAX * 128];
__device__ __align__(16) float  g_y[(size_t)NMAX * 64];
__device__ __align__(16) float4 g_pos4[NMAX];
__device__ int g_count[NMAX];
__device__ int g_offset[NMAX + 1];
__device__ int g_cursor[NMAX];
__device__ int g_esrc[EMAX];
__device__ long long g_scan_state[128];   // packed (flag<<32)|value

// ---------------- per-block edge dtype sniff ----------------
__device__ __forceinline__ int sniff_is64(const void* ei) {
    const int* p = (const int*)ei;
    int is64 = 1;
#pragma unroll
    for (int i = 1; i < 16; i += 2)
        if (__ldg(&p[i]) != 0) is64 = 0;
    return is64;
}

// ---------------- prep: zero hist + scan state, pad pos ----------------
__global__ void prep_kernel(const float* __restrict__ pos, int N) {
    int i = blockIdx.x * blockDim.x + threadIdx.x;
    if (i < N) {
        g_count[i] = 0;
        g_pos4[i] = make_float4(pos[3 * i + 0], pos[3 * i + 1], pos[3 * i + 2], 0.f);
    }
    if (i < 128) g_scan_state[i] = 0;
}

// ---------------- histogram of dst ----------------
__global__ __launch_bounds__(256) void hist_kernel(const void* __restrict__ ei, int E) {
    __shared__ int s_is64;
    if (threadIdx.x == 0) s_is64 = sniff_is64(ei);
    __syncthreads();
    int t = blockIdx.x * blockDim.x + threadIdx.x;
    if (t >= E) return;
    int d;
    if (s_is64) d = (int)((const long long*)ei)[(size_t)E + t];
    else        d = ((const int*)ei)[(size_t)E + t];
    atomicAdd(&g_count[d], 1);
}

// ---------------- single-pass scan with decoupled lookback ----------------
// grid = ceil(N/1024) <= 98 blocks, all co-resident on 148 SMs.
__global__ __launch_bounds__(SCAN_BLK) void scan_kernel(int N, int E) {
    __shared__ int s_warp[32];
    __shared__ int s_prefix;

    const int tid = threadIdx.x;
    const int b = blockIdx.x;
    const int lane = tid & 31;
    const int wid = tid >> 5;
    const int i = b * SCAN_BLK + tid;

    int v = (i < N) ? g_count[i] : 0;

    // warp inclusive scan
    int incl = v;
#pragma unroll
    for (int ofs = 1; ofs < 32; ofs <<= 1) {
        int t = __shfl_up_sync(0xffffffffu, incl, ofs);
        if (lane >= ofs) incl += t;
    }
    if (lane == 31) s_warp[wid] = incl;
    __syncthreads();

    if (wid == 0) {
        int wv = s_warp[lane];
#pragma unroll
        for (int ofs = 1; ofs < 32; ofs <<= 1) {
            int t = __shfl_up_sync(0xffffffffu, wv, ofs);
            if (lane >= ofs) wv += t;
        }
        s_warp[lane] = wv;
    }
    __syncthreads();

    int warp_excl = (wid == 0) ? 0 : s_warp[wid - 1];
    int block_incl = incl + warp_excl;
    int block_total = s_warp[31];

    // decoupled lookback (thread 0)
    if (tid == 0) {
        volatile long long* st = (volatile long long*)g_scan_state;
        long long agg = ((long long)1 << 32) | (unsigned)block_total;
        int prefix = 0;
        if (b == 0) {
            __threadfence();
            st[0] = ((long long)2 << 32) | (unsigned)block_total;
        } else {
            __threadfence();
            st[b] = agg;
            int j = b - 1;
            while (j >= 0) {
                long long s = st[j];
                int flag = (int)(s >> 32);
                if (flag == 2) { prefix += (int)(unsigned)s; break; }
                if (flag == 1) { prefix += (int)(unsigned)s; j--; }
                // flag==0: spin
            }
            __threadfence();
            st[b] = ((long long)2 << 32) | (unsigned)(prefix + block_total);
        }
        s_prefix = prefix;
    }
    __syncthreads();

    int off = s_prefix + block_incl - v;   // exclusive scan value
    if (i < N) {
        g_offset[i] = off;
        g_cursor[i] = off;
        if (i == N - 1) g_offset[N] = E;
    }
}

// ---------------- scatter: sort src ids by dst ----------------
__global__ __launch_bounds__(256) void scatter_kernel(const void* __restrict__ ei, int E) {
    __shared__ int s_is64;
    if (threadIdx.x == 0) s_is64 = sniff_is64(ei);
    __syncthreads();
    int t = blockIdx.x * blockDim.x + threadIdx.x;
    if (t >= E) return;
    int s, d;
    if (s_is64) {
        s = (int)((const long long*)ei)[t];
        d = (int)((const long long*)ei)[(size_t)E + t];
    } else {
        s = ((const int*)ei)[t];
        d = ((const int*)ei)[(size_t)E + t];
    }
    int idx = atomicAdd(&g_cursor[d], 1);
    g_esrc[idx] = s;
}

// ---------------- node projections (fp16 output, interleaved) ----------------
#define SX_STRIDE 68
__global__ __launch_bounds__(128) void proj_kernel(
    const float* __restrict__ x,
    const float* __restrict__ W_lin,
    const float* __restrict__ W_src,
    int N)
{
    const int c  = threadIdx.x;
    const int m  = c >> 6;
    const int cc = c & 63;
    const int h  = cc >> 4;
    const int k  = cc & 15;
    const int hidx = 4 * (cc >> 1) + (cc & 1) + 2 * m;
    const float* W = m ? W_src : W_lin;

    float w[64];
#pragma unroll
    for (int j = 0; j < 64; j++) w[j] = __ldg(&W[h * 1024 + j * 16 + k]);

    __shared__ float sx[64 * SX_STRIDE];

    const int base = blockIdx.x * 64;
    for (int f = threadIdx.x; f < 64 * 16; f += 128) {
        int node = f >> 4;
        int j4 = f & 15;
        int gn = base + node;
        if (gn >= N) gn = N - 1;
        float4 v = ((const float4*)x)[(size_t)gn * 16 + j4];
        int j = j4 * 4;
        sx[(j + 0) * SX_STRIDE + node] = v.x;
        sx[(j + 1) * SX_STRIDE + node] = v.y;
        sx[(j + 2) * SX_STRIDE + node] = v.z;
        sx[(j + 3) * SX_STRIDE + node] = v.w;
    }
    __syncthreads();

#pragma unroll
    for (int p = 0; p < 2; p++) {
        float acc[32];
#pragma unroll
        for (int r = 0; r < 32; r++) acc[r] = 0.f;
        for (int j = 0; j < 64; j++) {
            const float4* row = (const float4*)(sx + j * SX_STRIDE + p * 32);
            float wj = w[j];
#pragma unroll
            for (int q = 0; q < 8; q++) {
                float4 v = row[q];
                acc[q * 4 + 0] = fmaf(v.x, wj, acc[q * 4 + 0]);
                acc[q * 4 + 1] = fmaf(v.y, wj, acc[q * 4 + 1]);
                acc[q * 4 + 2] = fmaf(v.z, wj, acc[q * 4 + 2]);
                acc[q * 4 + 3] = fmaf(v.w, wj, acc[q * 4 + 3]);
            }
        }
#pragma unroll
        for (int r = 0; r < 32; r++) {
            int gn = base + p * 32 + r;
            if (gn < N) g_projh[(size_t)gn * 128 + hidx] = __float2half_rn(acc[r]);
        }
    }
}

// ---------------- per-destination-node attention: warp per node ----------------
__global__ __launch_bounds__(256) void node_kernel(
    const float* __restrict__ W_pos,
    const float* __restrict__ b_pos,
    int N)
{
    const int warp = threadIdx.x >> 5;
    const int l = threadIdx.x & 31;
    const int n = blockIdx.x * 8 + warp;
    if (n >= N) return;

    const int c0 = 2 * l;
    const int h  = c0 >> 4;
    const int k0 = c0 & 15;
    const int k1 = k0 + 1;

    const float w00 = __ldg(&W_pos[h * 48 + 0  + k0]);
    const float w10 = __ldg(&W_pos[h * 48 + 16 + k0]);
    const float w20 = __ldg(&W_pos[h * 48 + 32 + k0]);
    const float b0  = __ldg(&b_pos[h * 16 + k0]);
    const float w01 = __ldg(&W_pos[h * 48 + 0  + k1]);
    const float w11 = __ldg(&W_pos[h * 48 + 16 + k1]);
    const float w21 = __ldg(&W_pos[h * 48 + 32 + k1]);
    const float b1  = __ldg(&b_pos[h * 16 + k1]);

    const float4 pn = g_pos4[n];
    const int off = g_offset[n];
    const int end = g_offset[n + 1];

    // dual accumulator sets (break dependency chains under deep unroll)
    float denA0 = 0.f, denA1 = 0.f, acA0 = 0.f, acA1 = 0.f;
    float denB0 = 0.f, denB1 = 0.f, acB0 = 0.f, acB1 = 0.f;

    for (int base = off; base < end; base += 32) {
        int idx = base + l;
        int sid = (idx < end) ? g_esrc[idx] : 0;
        int cnt = min(32, end - base);
#pragma unroll 8
        for (int j = 0; j < cnt; j++) {
            int s = __shfl_sync(0xffffffffu, sid, j);
            float4 p = __ldg(&g_pos4[s]);
            uint2 u = __ldg((const uint2*)(g_projh + (size_t)s * 128) + l);
            float2 vl = __half22float2(*(const __half2*)&u.x);
            float2 va = __half22float2(*(const __half2*)&u.y);

            float rx = p.x - pn.x;
            float ry = p.y - pn.y;
            float rz = p.z - pn.z;

            float d0 = fmaf(rx, w00, fmaf(ry, w10, fmaf(rz, w20, b0)));
            float d1 = fmaf(rx, w01, fmaf(ry, w11, fmaf(rz, w21, b1)));

            float e0 = __expf(va.x + d0);
            float e1 = __expf(va.y + d1);

            if (j & 1) {
                denB0 += e0; denB1 += e1;
                acB0 = fmaf(e0, vl.x + d0, acB0);
                acB1 = fmaf(e1, vl.y + d1, acB1);
            } else {
                denA0 += e0; denA1 += e1;
                acA0 = fmaf(e0, vl.x + d0, acA0);
                acA1 = fmaf(e1, vl.y + d1, acA1);
            }
        }
    }

    float den0 = denA0 + denB0;
    float den1 = denA1 + denB1;
    float2 r;
    r.x = (acA0 + acB0) / (den0 + 1e-16f);
    r.y = (acA1 + acB1) / (den1 + 1e-16f);
    ((float2*)g_y)[(size_t)n * 32 + l] = r;
}

// ---------------- MLP: out = relu(y@W1+b1)@W2+b2, 64 nodes/block ----------------
__global__ __launch_bounds__(256) void mlp_kernel(
    const float* __restrict__ W1, const float* __restrict__ b1,
    const float* __restrict__ W2, const float* __restrict__ b2,
    float* __restrict__ out, int N)
{
    __shared__ float sW1[4096];
    __shared__ float sW2[4096];
    __shared__ float sy[4][64];
    __shared__ float sh_[4][64];

    for (int i = threadIdx.x; i < 4096; i += 256) {
        sW1[i] = W1[i];
        sW2[i] = W2[i];
    }

    const int i = threadIdx.x >> 6;
    const int o = threadIdx.x & 63;
    const float B1 = __ldg(&b1[o]);
    const float B2 = __ldg(&b2[o]);
    __syncthreads();

    for (int g = 0; g < 16; g++) {
        int n = blockIdx.x * 64 + g * 4 + i;
        float yv = (n < N) ? g_y[(size_t)n * 64 + o] : 0.f;
        sy[i][o] = yv;
        __syncthreads();

        float a = B1;
#pragma unroll
        for (int ci = 0; ci < 64; ci++) a = fmaf(sy[i][ci], sW1[ci * 64 + o], a);
        sh_[i][o] = fmaxf(a, 0.f);
        __syncthreads();

        float r = B2;
#pragma unroll
        for (int ci = 0; ci < 64; ci++) r = fmaf(sh_[i][ci], sW2[ci * 64 + o], r);
        if (n < N) out[(size_t)n * 64 + o] = r;
        __syncthreads();
    }
}

// ---------------- host ----------------
extern "C" void kernel_launch(void* const* d_in, const int* in_sizes, int n_in,
                              void* d_out, int out_size) {
    const float* x     = (const float*)d_in[0];
    const float* pos   = (const float*)d_in[1];
    const void*  ei    = d_in[2];
    const float* W_lin = (const float*)d_in[3];
    const float* W_src = (const float*)d_in[4];
    // d_in[5] = W_dst (cancels in the per-dst softmax)
    const float* W_pos = (const float*)d_in[6];
    const float* b_pos = (const float*)d_in[7];
    const float* W1    = (const float*)d_in[8];
    const float* b1    = (const float*)d_in[9];
    const float* W2    = (const float*)d_in[10];
    const float* b2    = (const float*)d_in[11];
    float* out = (float*)d_out;

    const int N = in_sizes[0] / 64;
    const int E = in_sizes[2] / 2;
    const int nb = (N + SCAN_BLK - 1) / SCAN_BLK;

    prep_kernel<<<(N + 255) / 256, 256>>>(pos, N);
    hist_kernel<<<(E + 255) / 256, 256>>>(ei, E);
    scan_kernel<<<nb, SCAN_BLK>>>(N, E);
    scatter_kernel<<<(E + 255) / 256, 256>>>(ei, E);
    proj_kernel<<<(N + 63) / 64, 128>>>(x, W_lin, W_src, N);
    node_kernel<<<(N + 7) / 8, 256>>>(W_pos, b_pos, N);
    mlp_kernel<<<(N + 63) / 64, 256>>>(W1, b1, W2, b2, out, N);
}

// round 7
// speedup vs baseline: 1.1706x; 1.1472x over previous
#include <cuda_runtime.h>
#include <cuda_fp16.h>
#include <cstdint>

#define NMAX 100000
#define EMAX 3200000
#define SCAN_BLK 1024

// ---------------- device scratch ----------------
__device__ __align__(16) __half g_projh[(size_t)NMAX * 128];
__device__ __align__(16) float  g_y[(size_t)NMAX * 64];
__device__ __align__(16) float4 g_pos4[NMAX];
__device__ int g_count[NMAX];
__device__ int g_offset[NMAX + 1];
__device__ int g_cursor[NMAX];
__device__ int g_esrc[EMAX];
__device__ long long g_scan_state[128];
__device__ int g_scan_count;
__device__ int g_scan_done;

// ---------------- per-block edge dtype sniff ----------------
__device__ __forceinline__ int sniff_is64(const void* ei) {
    const int* p = (const int*)ei;
    int is64 = 1;
#pragma unroll
    for (int i = 1; i < 16; i += 2)
        if (__ldg(&p[i]) != 0) is64 = 0;
    return is64;
}

// ---------------- fused prep + node projections ----------------
// 64 nodes/block, 128 threads. Also zeroes hist + scan state + pads pos.
#define SX_STRIDE 68
__global__ __launch_bounds__(128) void prepproj_kernel(
    const float* __restrict__ x,
    const float* __restrict__ pos,
    const float* __restrict__ W_lin,
    const float* __restrict__ W_src,
    int N)
{
    const int base = blockIdx.x * 64;

    // ---- prep part ----
    if (threadIdx.x < 64) {
        int n = base + threadIdx.x;
        if (n < N) {
            g_count[n] = 0;
            g_pos4[n] = make_float4(pos[3 * n + 0], pos[3 * n + 1], pos[3 * n + 2], 0.f);
        }
    }
    if (blockIdx.x == 0) {
        if (threadIdx.x < 128) g_scan_state[threadIdx.x] = 0;
        if (threadIdx.x == 0) { g_scan_count = 0; g_scan_done = 0; }
    }

    // ---- proj part ----
    const int c  = threadIdx.x;
    const int m  = c >> 6;
    const int cc = c & 63;
    const int h  = cc >> 4;
    const int k  = cc & 15;
    const int hidx = 4 * (cc >> 1) + (cc & 1) + 2 * m;
    const float* W = m ? W_src : W_lin;

    float w[64];
#pragma unroll
    for (int j = 0; j < 64; j++) w[j] = __ldg(&W[h * 1024 + j * 16 + k]);

    __shared__ float sx[64 * SX_STRIDE];

    for (int f = threadIdx.x; f < 64 * 16; f += 128) {
        int node = f >> 4;
        int j4 = f & 15;
        int gn = base + node;
        if (gn >= N) gn = N - 1;
        float4 v = ((const float4*)x)[(size_t)gn * 16 + j4];
        int j = j4 * 4;
        sx[(j + 0) * SX_STRIDE + node] = v.x;
        sx[(j + 1) * SX_STRIDE + node] = v.y;
        sx[(j + 2) * SX_STRIDE + node] = v.z;
        sx[(j + 3) * SX_STRIDE + node] = v.w;
    }
    __syncthreads();

#pragma unroll
    for (int p = 0; p < 2; p++) {
        float acc[32];
#pragma unroll
        for (int r = 0; r < 32; r++) acc[r] = 0.f;
        for (int j = 0; j < 64; j++) {
            const float4* row = (const float4*)(sx + j * SX_STRIDE + p * 32);
            float wj = w[j];
#pragma unroll
            for (int q = 0; q < 8; q++) {
                float4 v = row[q];
                acc[q * 4 + 0] = fmaf(v.x, wj, acc[q * 4 + 0]);
                acc[q * 4 + 1] = fmaf(v.y, wj, acc[q * 4 + 1]);
                acc[q * 4 + 2] = fmaf(v.z, wj, acc[q * 4 + 2]);
                acc[q * 4 + 3] = fmaf(v.w, wj, acc[q * 4 + 3]);
            }
        }
#pragma unroll
        for (int r = 0; r < 32; r++) {
            int gn = base + p * 32 + r;
            if (gn < N) g_projh[(size_t)gn * 128 + hidx] = __float2half_rn(acc[r]);
        }
    }
}

// ---------------- histogram of dst ----------------
__global__ __launch_bounds__(256) void hist_kernel(const void* __restrict__ ei, int E) {
    __shared__ int s_is64;
    if (threadIdx.x == 0) s_is64 = sniff_is64(ei);
    __syncthreads();
    int t = blockIdx.x * blockDim.x + threadIdx.x;
    if (t >= E) return;
    int d;
    if (s_is64) d = (int)((const long long*)ei)[(size_t)E + t];
    else        d = ((const int*)ei)[(size_t)E + t];
    atomicAdd(&g_count[d], 1);
}

// ---------------- fused scan (decoupled lookback) + scatter ----------------
// Blocks 0..nscan-1 scan the histogram; all blocks then scatter their edge chunk.
// nscan <= 98 blocks are guaranteed co-resident in wave 1 (>=2 blocks/SM * 148).
__global__ __launch_bounds__(SCAN_BLK) void scan_scatter_kernel(
    const void* __restrict__ ei, int N, int E, int nscan)
{
    __shared__ int s_warp[32];
    __shared__ int s_prefix;
    __shared__ int s_is64;

    const int tid = threadIdx.x;
    const int b = blockIdx.x;
    const int lane = tid & 31;
    const int wid = tid >> 5;

    if (b < nscan) {
        const int i = b * SCAN_BLK + tid;
        int v = (i < N) ? g_count[i] : 0;

        int incl = v;
#pragma unroll
        for (int ofs = 1; ofs < 32; ofs <<= 1) {
            int t = __shfl_up_sync(0xffffffffu, incl, ofs);
            if (lane >= ofs) incl += t;
        }
        if (lane == 31) s_warp[wid] = incl;
        __syncthreads();

        if (wid == 0) {
            int wv = s_warp[lane];
#pragma unroll
            for (int ofs = 1; ofs < 32; ofs <<= 1) {
                int t = __shfl_up_sync(0xffffffffu, wv, ofs);
                if (lane >= ofs) wv += t;
            }
            s_warp[lane] = wv;
        }
        __syncthreads();

        int warp_excl = (wid == 0) ? 0 : s_warp[wid - 1];
        int block_incl = incl + warp_excl;
        int block_total = s_warp[31];

        if (tid == 0) {
            volatile long long* st = (volatile long long*)g_scan_state;
            int prefix = 0;
            if (b == 0) {
                __threadfence();
                st[0] = ((long long)2 << 32) | (unsigned)block_total;
            } else {
                __threadfence();
                st[b] = ((long long)1 << 32) | (unsigned)block_total;
                int j = b - 1;
                while (j >= 0) {
                    long long s = st[j];
                    int flag = (int)(s >> 32);
                    if (flag == 2) { prefix += (int)(unsigned)s; break; }
                    if (flag == 1) { prefix += (int)(unsigned)s; j--; }
                }
                __threadfence();
                st[b] = ((long long)2 << 32) | (unsigned)(prefix + block_total);
            }
            s_prefix = prefix;
        }
        __syncthreads();

        int off = s_prefix + block_incl - v;
        if (i < N) {
            g_offset[i] = off;
            g_cursor[i] = off;
            if (i == N - 1) g_offset[N] = E;
        }
        __syncthreads();
        if (tid == 0) {
            __threadfence();
            int done = atomicAdd(&g_scan_count, 1);
            if (done == nscan - 1) atomicExch(&g_scan_done, 1);
        }
    }

    // wait for scan completion (scan blocks co-resident; deadlock-free)
    if (tid == 0) {
        while (atomicAdd(&g_scan_done, 0) == 0) { __nanosleep(64); }
        s_is64 = sniff_is64(ei);
    }
    __syncthreads();

    // scatter this block's edge chunk
    int t = b * SCAN_BLK + tid;
    if (t < E) {
        int s, d;
        if (s_is64) {
            s = (int)((const long long*)ei)[t];
            d = (int)((const long long*)ei)[(size_t)E + t];
        } else {
            s = ((const int*)ei)[t];
            d = ((const int*)ei)[(size_t)E + t];
        }
        int idx = atomicAdd(&g_cursor[d], 1);
        g_esrc[idx] = s;
    }
}

// ---------------- per-destination-node attention: warp per node ----------------
__global__ __launch_bounds__(256) void node_kernel(
    const float* __restrict__ W_pos,
    const float* __restrict__ b_pos,
    int N)
{
    const int warp = threadIdx.x >> 5;
    const int l = threadIdx.x & 31;
    const int n = blockIdx.x * 8 + warp;
    if (n >= N) return;

    const int c0 = 2 * l;
    const int h  = c0 >> 4;
    const int k0 = c0 & 15;
    const int k1 = k0 + 1;

    const float w00 = __ldg(&W_pos[h * 48 + 0  + k0]);
    const float w10 = __ldg(&W_pos[h * 48 + 16 + k0]);
    const float w20 = __ldg(&W_pos[h * 48 + 32 + k0]);
    const float b0  = __ldg(&b_pos[h * 16 + k0]);
    const float w01 = __ldg(&W_pos[h * 48 + 0  + k1]);
    const float w11 = __ldg(&W_pos[h * 48 + 16 + k1]);
    const float w21 = __ldg(&W_pos[h * 48 + 32 + k1]);
    const float b1  = __ldg(&b_pos[h * 16 + k1]);

    const float4 pn = g_pos4[n];
    const int off = g_offset[n];
    const int end = g_offset[n + 1];

    float den0 = 0.f, den1 = 0.f, ac0 = 0.f, ac1 = 0.f;

    int idx = off + l;
    int sid = (idx < end) ? g_esrc[idx] : 0;
    for (int base = off; base < end; base += 32) {
        // prefetch next batch's src id
        int nidx = base + 32 + l;
        int nsid = (nidx < end) ? g_esrc[nidx] : 0;
        int cnt = min(32, end - base);
#pragma unroll 4
        for (int j = 0; j < cnt; j++) {
            int s = __shfl_sync(0xffffffffu, sid, j);
            float4 p = __ldg(&g_pos4[s]);
            uint2 u = __ldg((const uint2*)(g_projh + (size_t)s * 128) + l);
            float2 vl = __half22float2(*(const __half2*)&u.x);
            float2 va = __half22float2(*(const __half2*)&u.y);

            float rx = p.x - pn.x;
            float ry = p.y - pn.y;
            float rz = p.z - pn.z;

            float d0 = fmaf(rx, w00, fmaf(ry, w10, fmaf(rz, w20, b0)));
            float d1 = fmaf(rx, w01, fmaf(ry, w11, fmaf(rz, w21, b1)));

            float e0 = __expf(va.x + d0);
            float e1 = __expf(va.y + d1);

            den0 += e0;
            den1 += e1;
            ac0 = fmaf(e0, vl.x + d0, ac0);
            ac1 = fmaf(e1, vl.y + d1, ac1);
        }
        sid = nsid;
    }

    float2 r;
    r.x = ac0 / (den0 + 1e-16f);
    r.y = ac1 / (den1 + 1e-16f);
    ((float2*)g_y)[(size_t)n * 32 + l] = r;
}

// ---------------- register-tiled MLP ----------------
// 64 nodes/block, 256 threads. Thread = (out-group og: 8 outs) x (node-group ng: 2 nodes).
// Shared: sy [k][node] 16KB, sh [o][node] 16KB, sW 16KB (W1 then W2). Total 48KB.
__global__ __launch_bounds__(256) void mlp_kernel(
    const float* __restrict__ W1, const float* __restrict__ b1,
    const float* __restrict__ W2, const float* __restrict__ b2,
    float* __restrict__ out, int N)
{
    __shared__ float sy[64 * 64];
    __shared__ float sh_[64 * 64];
    __shared__ float sW[64 * 64];

    const int tid = threadIdx.x;
    const int og = tid >> 5;        // 0..7  -> outputs og*8..og*8+7
    const int ng = tid & 31;        // 0..31 -> nodes 2ng, 2ng+1
    const int base = blockIdx.x * 64;

    // load y transposed to [k][node]
    for (int f = tid; f < 64 * 16; f += 256) {
        int node = f >> 4;
        int j4 = f & 15;
        int gn = base + node;
        float4 v = (gn < N) ? ((const float4*)g_y)[(size_t)gn * 16 + j4]
                            : make_float4(0.f, 0.f, 0.f, 0.f);
        int cch = j4 * 4;
        sy[(cch + 0) * 64 + node] = v.x;
        sy[(cch + 1) * 64 + node] = v.y;
        sy[(cch + 2) * 64 + node] = v.z;
        sy[(cch + 3) * 64 + node] = v.w;
    }
    // load W1
    for (int f = tid; f < 1024; f += 256)
        ((float4*)sW)[f] = ((const float4*)W1)[f];
    __syncthreads();

    // ---- layer 1 ----
    float acc[16];
    {
        float4 ba = *(const float4*)(b1 + og * 8);
        float4 bb = *(const float4*)(b1 + og * 8 + 4);
        acc[0]=ba.x; acc[1]=ba.y; acc[2]=ba.z; acc[3]=ba.w;
        acc[4]=bb.x; acc[5]=bb.y; acc[6]=bb.z; acc[7]=bb.w;
#pragma unroll
        for (int r = 0; r < 8; r++) acc[8 + r] = acc[r];
    }
#pragma unroll 8
    for (int k = 0; k < 64; k++) {
        float2 yv = *(const float2*)(sy + k * 64 + 2 * ng);
        float4 wa = *(const float4*)(sW + k * 64 + og * 8);
        float4 wb = *(const float4*)(sW + k * 64 + og * 8 + 4);
        acc[0]  = fmaf(yv.x, wa.x, acc[0]);
        acc[1]  = fmaf(yv.x, wa.y, acc[1]);
        acc[2]  = fmaf(yv.x, wa.z, acc[2]);
        acc[3]  = fmaf(yv.x, wa.w, acc[3]);
        acc[4]  = fmaf(yv.x, wb.x, acc[4]);
        acc[5]  = fmaf(yv.x, wb.y, acc[5]);
        acc[6]  = fmaf(yv.x, wb.z, acc[6]);
        acc[7]  = fmaf(yv.x, wb.w, acc[7]);
        acc[8]  = fmaf(yv.y, wa.x, acc[8]);
        acc[9]  = fmaf(yv.y, wa.y, acc[9]);
        acc[10] = fmaf(yv.y, wa.z, acc[10]);
        acc[11] = fmaf(yv.y, wa.w, acc[11]);
        acc[12] = fmaf(yv.y, wb.x, acc[12]);
        acc[13] = fmaf(yv.y, wb.y, acc[13]);
        acc[14] = fmaf(yv.y, wb.z, acc[14]);
        acc[15] = fmaf(yv.y, wb.w, acc[15]);
    }
    // relu + store h transposed [o][node]
#pragma unroll
    for (int oo = 0; oo < 8; oo++) {
        float2 hv;
        hv.x = fmaxf(acc[oo], 0.f);
        hv.y = fmaxf(acc[8 + oo], 0.f);
        *(float2*)(sh_ + (og * 8 + oo) * 64 + 2 * ng) = hv;
    }
    __syncthreads();

    // load W2 (reuse sW)
    for (int f = tid; f < 1024; f += 256)
        ((float4*)sW)[f] = ((const float4*)W2)[f];
    __syncthreads();

    // ---- layer 2 ----
    {
        float4 ba = *(const float4*)(b2 + og * 8);
        float4 bb = *(const float4*)(b2 + og * 8 + 4);
        acc[0]=ba.x; acc[1]=ba.y; acc[2]=ba.z; acc[3]=ba.w;
        acc[4]=bb.x; acc[5]=bb.y; acc[6]=bb.z; acc[7]=bb.w;
#pragma unroll
        for (int r = 0; r < 8; r++) acc[8 + r] = acc[r];
    }
#pragma unroll 8
    for (int k = 0; k < 64; k++) {
        float2 hv = *(const float2*)(sh_ + k * 64 + 2 * ng);
        float4 wa = *(const float4*)(sW + k * 64 + og * 8);
        float4 wb = *(const float4*)(sW + k * 64 + og * 8 + 4);
        acc[0]  = fmaf(hv.x, wa.x, acc[0]);
        acc[1]  = fmaf(hv.x, wa.y, acc[1]);
        acc[2]  = fmaf(hv.x, wa.z, acc[2]);
        acc[3]  = fmaf(hv.x, wa.w, acc[3]);
        acc[4]  = fmaf(hv.x, wb.x, acc[4]);
        acc[5]  = fmaf(hv.x, wb.y, acc[5]);
        acc[6]  = fmaf(hv.x, wb.z, acc[6]);
        acc[7]  = fmaf(hv.x, wb.w, acc[7]);
        acc[8]  = fmaf(hv.y, wa.x, acc[8]);
        acc[9]  = fmaf(hv.y, wa.y, acc[9]);
        acc[10] = fmaf(hv.y, wa.z, acc[10]);
        acc[11] = fmaf(hv.y, wa.w, acc[11]);
        acc[12] = fmaf(hv.y, wb.x, acc[12]);
        acc[13] = fmaf(hv.y, wb.y, acc[13]);
        acc[14] = fmaf(hv.y, wb.z, acc[14]);
        acc[15] = fmaf(hv.y, wb.w, acc[15]);
    }

    // write out: 2 nodes x 8 consecutive outputs each
#pragma unroll
    for (int nn = 0; nn < 2; nn++) {
        int gn = base + 2 * ng + nn;
        if (gn < N) {
            float4 oa, ob;
            oa.x = acc[8 * nn + 0]; oa.y = acc[8 * nn + 1];
            oa.z = acc[8 * nn + 2]; oa.w = acc[8 * nn + 3];
            ob.x = acc[8 * nn + 4]; ob.y = acc[8 * nn + 5];
            ob.z = acc[8 * nn + 6]; ob.w = acc[8 * nn + 7];
            *(float4*)(out + (size_t)gn * 64 + og * 8)     = oa;
            *(float4*)(out + (size_t)gn * 64 + og * 8 + 4) = ob;
        }
    }
}

// ---------------- host ----------------
extern "C" void kernel_launch(void* const* d_in, const int* in_sizes, int n_in,
                              void* d_out, int out_size) {
    const float* x     = (const float*)d_in[0];
    const float* pos   = (const float*)d_in[1];
    const void*  ei    = d_in[2];
    const float* W_lin = (const float*)d_in[3];
    const float* W_src = (const float*)d_in[4];
    // d_in[5] = W_dst (cancels in the per-dst softmax)
    const float* W_pos = (const float*)d_in[6];
    const float* b_pos = (const float*)d_in[7];
    const float* W1    = (const float*)d_in[8];
    const float* b1    = (const float*)d_in[9];
    const float* W2    = (const float*)d_in[10];
    const float* b2    = (const float*)d_in[11];
    float* out = (float*)d_out;

    const int N = in_sizes[0] / 64;
    const int E = in_sizes[2] / 2;
    const int nscan = (N + SCAN_BLK - 1) / SCAN_BLK;
    int nss = (E + SCAN_BLK - 1) / SCAN_BLK;
    if (nss < nscan) nss = nscan;

    prepproj_kernel<<<(N + 63) / 64, 128>>>(x, pos, W_lin, W_src, N);
    hist_kernel<<<(E + 255) / 256, 256>>>(ei, E);
    scan_scatter_kernel<<<nss, SCAN_BLK>>>(ei, N, E, nscan);
    node_kernel<<<(N + 7) / 8, 256>>>(W_pos, b_pos, N);
    mlp_kernel<<<(N + 63) / 64, 256>>>(W1, b1, W2, b2, out, N);
}

// round 8
// speedup vs baseline: 1.2551x; 1.0722x over previous
#include <cuda_runtime.h>
#include <cuda_fp16.h>
#include <cstdint>

#define NMAX 100000
#define EMAX 3200000
#define SCAN_BLK 1024

// ---------------- device scratch ----------------
__device__ __align__(16) __half g_projh[(size_t)NMAX * 128];
__device__ __align__(16) float  g_y[(size_t)NMAX * 64];
__device__ __align__(16) float4 g_pos4[NMAX];
__device__ __align__(16) float4 g_edge[EMAX];   // {src_as_float, rx, ry, rz}
__device__ int g_count[NMAX];
__device__ int g_offset[NMAX + 1];
__device__ int g_cursor[NMAX];
__device__ long long g_scan_state[128];
__device__ int g_scan_count;
__device__ int g_scan_done;

// ---------------- per-block edge dtype sniff ----------------
__device__ __forceinline__ int sniff_is64(const void* ei) {
    const int* p = (const int*)ei;
    int is64 = 1;
#pragma unroll
    for (int i = 1; i < 16; i += 2)
        if (__ldg(&p[i]) != 0) is64 = 0;
    return is64;
}

// ---------------- fused prep + node projections ----------------
#define SX_STRIDE 68
__global__ __launch_bounds__(128) void prepproj_kernel(
    const float* __restrict__ x,
    const float* __restrict__ pos,
    const float* __restrict__ W_lin,
    const float* __restrict__ W_src,
    int N)
{
    const int base = blockIdx.x * 64;

    if (threadIdx.x < 64) {
        int n = base + threadIdx.x;
        if (n < N) {
            g_count[n] = 0;
            g_pos4[n] = make_float4(pos[3 * n + 0], pos[3 * n + 1], pos[3 * n + 2], 0.f);
        }
    }
    if (blockIdx.x == 0) {
        if (threadIdx.x < 128) g_scan_state[threadIdx.x] = 0;
        if (threadIdx.x == 0) { g_scan_count = 0; g_scan_done = 0; }
    }

    const int c  = threadIdx.x;
    const int m  = c >> 6;
    const int cc = c & 63;
    const int h  = cc >> 4;
    const int k  = cc & 15;
    const int hidx = 4 * (cc >> 1) + (cc & 1) + 2 * m;
    const float* W = m ? W_src : W_lin;

    float w[64];
#pragma unroll
    for (int j = 0; j < 64; j++) w[j] = __ldg(&W[h * 1024 + j * 16 + k]);

    __shared__ float sx[64 * SX_STRIDE];

    for (int f = threadIdx.x; f < 64 * 16; f += 128) {
        int node = f >> 4;
        int j4 = f & 15;
        int gn = base + node;
        if (gn >= N) gn = N - 1;
        float4 v = ((const float4*)x)[(size_t)gn * 16 + j4];
        int j = j4 * 4;
        sx[(j + 0) * SX_STRIDE + node] = v.x;
        sx[(j + 1) * SX_STRIDE + node] = v.y;
        sx[(j + 2) * SX_STRIDE + node] = v.z;
        sx[(j + 3) * SX_STRIDE + node] = v.w;
    }
    __syncthreads();

#pragma unroll
    for (int p = 0; p < 2; p++) {
        float acc[32];
#pragma unroll
        for (int r = 0; r < 32; r++) acc[r] = 0.f;
        for (int j = 0; j < 64; j++) {
            const float4* row = (const float4*)(sx + j * SX_STRIDE + p * 32);
            float wj = w[j];
#pragma unroll
            for (int q = 0; q < 8; q++) {
                float4 v = row[q];
                acc[q * 4 + 0] = fmaf(v.x, wj, acc[q * 4 + 0]);
                acc[q * 4 + 1] = fmaf(v.y, wj, acc[q * 4 + 1]);
                acc[q * 4 + 2] = fmaf(v.z, wj, acc[q * 4 + 2]);
                acc[q * 4 + 3] = fmaf(v.w, wj, acc[q * 4 + 3]);
            }
        }
#pragma unroll
        for (int r = 0; r < 32; r++) {
            int gn = base + p * 32 + r;
            if (gn < N) g_projh[(size_t)gn * 128 + hidx] = __float2half_rn(acc[r]);
        }
    }
}

// ---------------- histogram of dst ----------------
__global__ __launch_bounds__(256) void hist_kernel(const void* __restrict__ ei, int E) {
    __shared__ int s_is64;
    if (threadIdx.x == 0) s_is64 = sniff_is64(ei);
    __syncthreads();
    int t = blockIdx.x * blockDim.x + threadIdx.x;
    if (t >= E) return;
    int d;
    if (s_is64) d = (int)((const long long*)ei)[(size_t)E + t];
    else        d = ((const int*)ei)[(size_t)E + t];
    atomicAdd(&g_count[d], 1);
}

// ---------------- fused scan (decoupled lookback) + scatter edge records ----------------
__global__ __launch_bounds__(SCAN_BLK) void scan_scatter_kernel(
    const void* __restrict__ ei, int N, int E, int nscan)
{
    __shared__ int s_warp[32];
    __shared__ int s_prefix;
    __shared__ int s_is64;

    const int tid = threadIdx.x;
    const int b = blockIdx.x;
    const int lane = tid & 31;
    const int wid = tid >> 5;

    if (b < nscan) {
        const int i = b * SCAN_BLK + tid;
        int v = (i < N) ? g_count[i] : 0;

        int incl = v;
#pragma unroll
        for (int ofs = 1; ofs < 32; ofs <<= 1) {
            int t = __shfl_up_sync(0xffffffffu, incl, ofs);
            if (lane >= ofs) incl += t;
        }
        if (lane == 31) s_warp[wid] = incl;
        __syncthreads();

        if (wid == 0) {
            int wv = s_warp[lane];
#pragma unroll
            for (int ofs = 1; ofs < 32; ofs <<= 1) {
                int t = __shfl_up_sync(0xffffffffu, wv, ofs);
                if (lane >= ofs) wv += t;
            }
            s_warp[lane] = wv;
        }
        __syncthreads();

        int warp_excl = (wid == 0) ? 0 : s_warp[wid - 1];
        int block_incl = incl + warp_excl;
        int block_total = s_warp[31];

        if (tid == 0) {
            volatile long long* st = (volatile long long*)g_scan_state;
            int prefix = 0;
            if (b == 0) {
                __threadfence();
                st[0] = ((long long)2 << 32) | (unsigned)block_total;
            } else {
                __threadfence();
                st[b] = ((long long)1 << 32) | (unsigned)block_total;
                int j = b - 1;
                while (j >= 0) {
                    long long s = st[j];
                    int flag = (int)(s >> 32);
                    if (flag == 2) { prefix += (int)(unsigned)s; break; }
                    if (flag == 1) { prefix += (int)(unsigned)s; j--; }
                }
                __threadfence();
                st[b] = ((long long)2 << 32) | (unsigned)(prefix + block_total);
            }
            s_prefix = prefix;
        }
        __syncthreads();

        int off = s_prefix + block_incl - v;
        if (i < N) {
            g_offset[i] = off;
            g_cursor[i] = off;
            if (i == N - 1) g_offset[N] = E;
        }
        __syncthreads();
        if (tid == 0) {
            __threadfence();
            int done = atomicAdd(&g_scan_count, 1);
            if (done == nscan - 1) atomicExch(&g_scan_done, 1);
        }
    }

    if (tid == 0) {
        while (atomicAdd(&g_scan_done, 0) == 0) { __nanosleep(64); }
        s_is64 = sniff_is64(ei);
    }
    __syncthreads();

    int t = b * SCAN_BLK + tid;
    if (t < E) {
        int s, d;
        if (s_is64) {
            s = (int)((const long long*)ei)[t];
            d = (int)((const long long*)ei)[(size_t)E + t];
        } else {
            s = ((const int*)ei)[t];
            d = ((const int*)ei)[(size_t)E + t];
        }
        int idx = atomicAdd(&g_cursor[d], 1);
        float4 ps = __ldg(&g_pos4[s]);
        float4 pd = __ldg(&g_pos4[d]);
        float4 er;
        er.x = __int_as_float(s);
        er.y = ps.x - pd.x;
        er.z = ps.y - pd.y;
        er.w = ps.z - pd.z;
        g_edge[idx] = er;
    }
}

// ---------------- per-destination-node attention: warp per node ----------------
__global__ __launch_bounds__(256, 6) void node_kernel(
    const float* __restrict__ W_pos,
    const float* __restrict__ b_pos,
    int N)
{
    const int warp = threadIdx.x >> 5;
    const int l = threadIdx.x & 31;
    const int n = blockIdx.x * 8 + warp;
    if (n >= N) return;

    const int c0 = 2 * l;
    const int h  = c0 >> 4;
    const int k0 = c0 & 15;
    const int k1 = k0 + 1;

    const float w00 = __ldg(&W_pos[h * 48 + 0  + k0]);
    const float w10 = __ldg(&W_pos[h * 48 + 16 + k0]);
    const float w20 = __ldg(&W_pos[h * 48 + 32 + k0]);
    const float b0  = __ldg(&b_pos[h * 16 + k0]);
    const float w01 = __ldg(&W_pos[h * 48 + 0  + k1]);
    const float w11 = __ldg(&W_pos[h * 48 + 16 + k1]);
    const float w21 = __ldg(&W_pos[h * 48 + 32 + k1]);
    const float b1  = __ldg(&b_pos[h * 16 + k1]);

    const int off = g_offset[n];
    const int end = g_offset[n + 1];

    float den0 = 0.f, den1 = 0.f, ac0 = 0.f, ac1 = 0.f;

#pragma unroll 4
    for (int e = off; e < end; e++) {
        float4 er = __ldg(&g_edge[e]);                 // broadcast, 1 wavefront
        int s = __float_as_int(er.x);
        uint2 u = __ldg((const uint2*)(g_projh + (size_t)s * 128) + l);
        float2 vl = __half22float2(*(const __half2*)&u.x);
        float2 va = __half22float2(*(const __half2*)&u.y);

        float d0 = fmaf(er.y, w00, fmaf(er.z, w10, fmaf(er.w, w20, b0)));
        float d1 = fmaf(er.y, w01, fmaf(er.z, w11, fmaf(er.w, w21, b1)));

        float e0 = __expf(va.x + d0);
        float e1 = __expf(va.y + d1);

        den0 += e0;
        den1 += e1;
        ac0 = fmaf(e0, vl.x + d0, ac0);
        ac1 = fmaf(e1, vl.y + d1, ac1);
    }

    float2 r;
    r.x = ac0 / (den0 + 1e-16f);
    r.y = ac1 / (den1 + 1e-16f);
    ((float2*)g_y)[(size_t)n * 32 + l] = r;
}

// ---------------- register-tiled MLP ----------------
__global__ __launch_bounds__(256) void mlp_kernel(
    const float* __restrict__ W1, const float* __restrict__ b1,
    const float* __restrict__ W2, const float* __restrict__ b2,
    float* __restrict__ out, int N)
{
    __shared__ float sy[64 * 64];
    __shared__ float sh_[64 * 64];
    __shared__ float sW[64 * 64];

    const int tid = threadIdx.x;
    const int og = tid >> 5;
    const int ng = tid & 31;
    const int base = blockIdx.x * 64;

    for (int f = tid; f < 64 * 16; f += 256) {
        int node = f >> 4;
        int j4 = f & 15;
        int gn = base + node;
        float4 v = (gn < N) ? ((const float4*)g_y)[(size_t)gn * 16 + j4]
                            : make_float4(0.f, 0.f, 0.f, 0.f);
        int cch = j4 * 4;
        sy[(cch + 0) * 64 + node] = v.x;
        sy[(cch + 1) * 64 + node] = v.y;
        sy[(cch + 2) * 64 + node] = v.z;
        sy[(cch + 3) * 64 + node] = v.w;
    }
    for (int f = tid; f < 1024; f += 256)
        ((float4*)sW)[f] = ((const float4*)W1)[f];
    __syncthreads();

    float acc[16];
    {
        float4 ba = *(const float4*)(b1 + og * 8);
        float4 bb = *(const float4*)(b1 + og * 8 + 4);
        acc[0]=ba.x; acc[1]=ba.y; acc[2]=ba.z; acc[3]=ba.w;
        acc[4]=bb.x; acc[5]=bb.y; acc[6]=bb.z; acc[7]=bb.w;
#pragma unroll
        for (int r = 0; r < 8; r++) acc[8 + r] = acc[r];
    }
#pragma unroll 8
    for (int k = 0; k < 64; k++) {
        float2 yv = *(const float2*)(sy + k * 64 + 2 * ng);
        float4 wa = *(const float4*)(sW + k * 64 + og * 8);
        float4 wb = *(const float4*)(sW + k * 64 + og * 8 + 4);
        acc[0]  = fmaf(yv.x, wa.x, acc[0]);
        acc[1]  = fmaf(yv.x, wa.y, acc[1]);
        acc[2]  = fmaf(yv.x, wa.z, acc[2]);
        acc[3]  = fmaf(yv.x, wa.w, acc[3]);
        acc[4]  = fmaf(yv.x, wb.x, acc[4]);
        acc[5]  = fmaf(yv.x, wb.y, acc[5]);
        acc[6]  = fmaf(yv.x, wb.z, acc[6]);
        acc[7]  = fmaf(yv.x, wb.w, acc[7]);
        acc[8]  = fmaf(yv.y, wa.x, acc[8]);
        acc[9]  = fmaf(yv.y, wa.y, acc[9]);
        acc[10] = fmaf(yv.y, wa.z, acc[10]);
        acc[11] = fmaf(yv.y, wa.w, acc[11]);
        acc[12] = fmaf(yv.y, wb.x, acc[12]);
        acc[13] = fmaf(yv.y, wb.y, acc[13]);
        acc[14] = fmaf(yv.y, wb.z, acc[14]);
        acc[15] = fmaf(yv.y, wb.w, acc[15]);
    }
#pragma unroll
    for (int oo = 0; oo < 8; oo++) {
        float2 hv;
        hv.x = fmaxf(acc[oo], 0.f);
        hv.y = fmaxf(acc[8 + oo], 0.f);
        *(float2*)(sh_ + (og * 8 + oo) * 64 + 2 * ng) = hv;
    }
    __syncthreads();

    for (int f = tid; f < 1024; f += 256)
        ((float4*)sW)[f] = ((const float4*)W2)[f];
    __syncthreads();

    {
        float4 ba = *(const float4*)(b2 + og * 8);
        float4 bb = *(const float4*)(b2 + og * 8 + 4);
        acc[0]=ba.x; acc[1]=ba.y; acc[2]=ba.z; acc[3]=ba.w;
        acc[4]=bb.x; acc[5]=bb.y; acc[6]=bb.z; acc[7]=bb.w;
#pragma unroll
        for (int r = 0; r < 8; r++) acc[8 + r] = acc[r];
    }
#pragma unroll 8
    for (int k = 0; k < 64; k++) {
        float2 hv = *(const float2*)(sh_ + k * 64 + 2 * ng);
        float4 wa = *(const float4*)(sW + k * 64 + og * 8);
        float4 wb = *(const float4*)(sW + k * 64 + og * 8 + 4);
        acc[0]  = fmaf(hv.x, wa.x, acc[0]);
        acc[1]  = fmaf(hv.x, wa.y, acc[1]);
        acc[2]  = fmaf(hv.x, wa.z, acc[2]);
        acc[3]  = fmaf(hv.x, wa.w, acc[3]);
        acc[4]  = fmaf(hv.x, wb.x, acc[4]);
        acc[5]  = fmaf(hv.x, wb.y, acc[5]);
        acc[6]  = fmaf(hv.x, wb.z, acc[6]);
        acc[7]  = fmaf(hv.x, wb.w, acc[7]);
        acc[8]  = fmaf(hv.y, wa.x, acc[8]);
        acc[9]  = fmaf(hv.y, wa.y, acc[9]);
        acc[10] = fmaf(hv.y, wa.z, acc[10]);
        acc[11] = fmaf(hv.y, wa.w, acc[11]);
        acc[12] = fmaf(hv.y, wb.x, acc[12]);
        acc[13] = fmaf(hv.y, wb.y, acc[13]);
        acc[14] = fmaf(hv.y, wb.z, acc[14]);
        acc[15] = fmaf(hv.y, wb.w, acc[15]);
    }

#pragma unroll
    for (int nn = 0; nn < 2; nn++) {
        int gn = base + 2 * ng + nn;
        if (gn < N) {
            float4 oa, ob;
            oa.x = acc[8 * nn + 0]; oa.y = acc[8 * nn + 1];
            oa.z = acc[8 * nn + 2]; oa.w = acc[8 * nn + 3];
            ob.x = acc[8 * nn + 4]; ob.y = acc[8 * nn + 5];
            ob.z = acc[8 * nn + 6]; ob.w = acc[8 * nn + 7];
            *(float4*)(out + (size_t)gn * 64 + og * 8)     = oa;
            *(float4*)(out + (size_t)gn * 64 + og * 8 + 4) = ob;
        }
    }
}

// ---------------- host ----------------
extern "C" void kernel_launch(void* const* d_in, const int* in_sizes, int n_in,
                              void* d_out, int out_size) {
    const float* x     = (const float*)d_in[0];
    const float* pos   = (const float*)d_in[1];
    const void*  ei    = d_in[2];
    const float* W_lin = (const float*)d_in[3];
    const float* W_src = (const float*)d_in[4];
    // d_in[5] = W_dst (cancels in the per-dst softmax)
    const float* W_pos = (const float*)d_in[6];
    const float* b_pos = (const float*)d_in[7];
    const float* W1    = (const float*)d_in[8];
    const float* b1    = (const float*)d_in[9];
    const float* W2    = (const float*)d_in[10];
    const float* b2    = (const float*)d_in[11];
    float* out = (float*)d_out;

    const int N = in_sizes[0] / 64;
    const int E = in_sizes[2] / 2;
    const int nscan = (N + SCAN_BLK - 1) / SCAN_BLK;
    int nss = (E + SCAN_BLK - 1) / SCAN_BLK;
    if (nss < nscan) nss = nscan;

    prepproj_kernel<<<(N + 63) / 64, 128>>>(x, pos, W_lin, W_src, N);
    hist_kernel<<<(E + 255) / 256, 256>>>(ei, E);
    scan_scatter_kernel<<<nss, SCAN_BLK>>>(ei, N, E, nscan);
    node_kernel<<<(N + 7) / 8, 256>>>(W_pos, b_pos, N);
    mlp_kernel<<<(N + 63) / 64, 256>>>(W1, b1, W2, b2, out, N);
}